// round 15
// baseline (speedup 1.0000x reference)
#include <cuda_runtime.h>
#include <cstdint>

#define BB 32
#define NN 4096
#define DD 768
#define KK 1024
#define CHUNK 512
#define NCHUNK 8

typedef unsigned long long u64;

__device__ u64 g_scratch[BB * NN];   // per-batch: 8 sorted descending chunks

// Map float to uint with ascending unsigned order == ascending float order.
__device__ __forceinline__ unsigned f2ord(float f) {
    unsigned u = __float_as_uint(f);
    return (u & 0x80000000u) ? ~u : (u | 0x80000000u);
}

// ---------------------------------------------------------------------------
// Kernel A (R11 exact, measured 8.2us): CTA (b,c) sorts 512-element chunk c
// of batch b descending by composite key (ord << 12) | (4095 - idx)
// => jax.lax.top_k order (value desc, index asc). Keys strictly distinct.
// 1 key/thread, 512 threads, 256 CTAs.
// ---------------------------------------------------------------------------
__global__ __launch_bounds__(512) void sort_chunk_kernel(const float* __restrict__ sig) {
    __shared__ u64 sm[CHUNK];
    const int b = blockIdx.x >> 3;
    const int c = blockIdx.x & 7;
    const int t = threadIdx.x;

    const int g = c * CHUNK + t;
    float v = sig[(size_t)b * NN + g];
    u64 r = ((u64)f2ord(v) << 12) | (u64)(4095 - g);

    #pragma unroll
    for (int k = 2; k <= CHUNK; k <<= 1) {
        #pragma unroll
        for (int j = k >> 1; j > 0; j >>= 1) {
            bool keep_max = (((t & k) == 0) == ((t & j) == 0));
            u64 o;
            if (j >= 32) {
                __syncthreads();
                sm[t] = r;
                __syncthreads();
                o = sm[t ^ j];
            } else {
                o = __shfl_xor_sync(0xffffffffu, r, j);
            }
            r = keep_max ? (r > o ? r : o) : (r < o ? r : o);
        }
    }

    g_scratch[(size_t)b * NN + g] = r;
}

// ---------------------------------------------------------------------------
// Kernel B: FUSED rank-merge + gather. CTA (b,c), 512 threads.
//  1) rank each element of chunk c against the other 7 sorted chunks via 7
//     interleaved 9-step binary searches in smem, with the saturation fix
//     (search caps at 511 but true count can be 512: add (chunk_min > key)).
//     Ranks are a permutation of 0..4095 (keys strictly distinct).
//  2) compact winners (rank < 1024) into a smem list (atomicAdd order is
//     nondeterministic but copies are addressed by rank => output
//     deterministic). CTA c==0 appends a sentinel (rank=-1, idx=-1) so the
//     CLS row copies via the same arithmetic: out row 1+(-1)=0, src 1+(-1)=0.
//  3) flat cooperative copy: out[b, 1+rank] = x[b, 1+idx], 192 float4/row,
//     streaming loads+stores (rows touched at most once).
// ---------------------------------------------------------------------------
__global__ __launch_bounds__(512) void merge_gather_kernel(const float4* __restrict__ x,
                                                           float4* __restrict__ out) {
    __shared__ u64 sm[(NCHUNK - 1) * CHUNK];   // 7 x 512 keys = 28 KB
    __shared__ int w_rank[CHUNK + 1];
    __shared__ int w_idx[CHUNK + 1];
    __shared__ int wcount;

    const int b = blockIdx.x >> 3;
    const int c = blockIdx.x & 7;
    const int t = threadIdx.x;

    cudaGridDependencySynchronize();           // sort kernel fully complete

    if (t == 0) wcount = 0;

    const u64* base = g_scratch + (size_t)b * NN;

    #pragma unroll
    for (int o = 0; o < NCHUNK - 1; o++) {
        int oc = o + (o >= c ? 1 : 0);
        sm[o * CHUNK + t] = base[oc * CHUNK + t];
    }

    u64 key = base[c * CHUNK + t];
    __syncthreads();                           // covers wcount init + sm loads

    int cnt[NCHUNK - 1];
    #pragma unroll
    for (int o = 0; o < NCHUNK - 1; o++) cnt[o] = 0;

    #pragma unroll
    for (int s = CHUNK / 2; s >= 1; s >>= 1) {
        #pragma unroll
        for (int o = 0; o < NCHUNK - 1; o++) {
            if (sm[o * CHUNK + cnt[o] + s - 1] > key) cnt[o] += s;
        }
    }

    int rank = t;
    #pragma unroll
    for (int o = 0; o < NCHUNK - 1; o++) {
        // saturation fix: whole chunk greater => true count is CHUNK
        rank += cnt[o] + (sm[o * CHUNK + CHUNK - 1] > key ? 1 : 0);
    }

    // 2) winner compaction (+ CLS sentinel in chunk-0 CTAs)
    if (rank < KK) {
        int slot = atomicAdd(&wcount, 1);
        w_rank[slot] = rank;
        w_idx[slot]  = 4095 - (int)(key & 0xFFFu);
    }
    if (c == 0 && t == 0) {
        int slot = atomicAdd(&wcount, 1);
        w_rank[slot] = -1;                     // out row 0 (CLS)
        w_idx[slot]  = -1;                     // src row 0 (CLS)
    }
    __syncthreads();

    // 3) cooperative row copy (flat over winners x 192 float4)
    const int nw    = wcount;
    const int total = nw * (DD / 4);
    const float4* xb   = x   + (size_t)b * (NN + 1) * (DD / 4);
    float4*       outb = out + (size_t)b * (KK + 1) * (DD / 4);

    #pragma unroll 4
    for (int i = t; i < total; i += 512) {
        int row = i / (DD / 4);
        int col = i - row * (DD / 4);
        float4 v = __ldcs(xb + (size_t)(1 + w_idx[row]) * (DD / 4) + col);
        __stcs(outb + (size_t)(1 + w_rank[row]) * (DD / 4) + col, v);
    }
}

extern "C" void kernel_launch(void* const* d_in, const int* in_sizes, int n_in,
                              void* d_out, int out_size) {
    const float* x   = (const float*)d_in[0];   // [B, N+1, D] fp32
    const float* sig = (const float*)d_in[1];   // [B, N] fp32
    (void)in_sizes; (void)n_in; (void)out_size;

    sort_chunk_kernel<<<BB * NCHUNK, CHUNK>>>(sig);

    cudaLaunchAttribute attr[1];
    attr[0].id = cudaLaunchAttributeProgrammaticStreamSerialization;
    attr[0].val.programmaticStreamSerializationAllowed = 1;

    cudaLaunchConfig_t cfg = {};
    cfg.gridDim  = dim3(BB * NCHUNK);
    cfg.blockDim = dim3(CHUNK);
    cfg.stream   = 0;
    cfg.attrs    = attr;
    cfg.numAttrs = 1;
    cudaLaunchKernelEx(&cfg, merge_gather_kernel, (const float4*)x, (float4*)d_out);
}